// round 15
// baseline (speedup 1.0000x reference)
#include <cuda_runtime.h>
#include <cuda_fp16.h>
#include <cstdint>

#define NNODES 25000
#define NEDGES 400000
#define DIM    1024
#define MPAD   25088          // 196 * 128
#define KDUAL  2048
#define BK     64
#define NSTAGE_H 16           // 1024 / BK per K-half
#define NBUF   3
#define STAGE_BYTES 24576     // A 16K + B 8K
#define SMEMSZ (NBUF * STAGE_BYTES + 1024)

// ---------------- device scratch ---------------------------------------------
__device__ int   g_deg[NNODES];
__device__ float g_deginv[NNODES];
__device__ int   g_rowptr[NNODES + 1];
__device__ int   g_fill[NNODES];
__device__ int   g_col[NEDGES];
__device__ __align__(256) __half g_A0[(size_t)MPAD * KDUAL];   // [x | mean(x)] fp16
__device__ __align__(256) __half g_A1[(size_t)MPAD * KDUAL];   // [h | mean(h)] fp16
__device__ __align__(256) __half g_B0[(size_t)DIM * KDUAL];    // layer-0 [N][K] fp16(W^T)
__device__ __align__(256) __half g_B1[(size_t)DIM * KDUAL];    // layer-1 [N][K] fp16(W^T)
__device__ __align__(256) float  g_C[(size_t)MPAD * DIM];      // fp32 K-half partials

// ---------------- helpers ------------------------------------------------------
__device__ __forceinline__ uint32_t smem_u32_of(const void* p) {
    uint32_t a;
    asm("{ .reg .u64 t; cvta.to.shared.u64 t, %1; cvt.u32.u64 %0, t; }" : "=r"(a) : "l"(p));
    return a;
}

__device__ __forceinline__ uint32_t sw128(uint32_t off) {
    return off ^ ((off >> 3) & 0x70);
}

__device__ __forceinline__ void cp_async16(uint32_t saddr, const void* g) {
    asm volatile("cp.async.cg.shared.global [%0], [%1], 16;" :: "r"(saddr), "l"(g));
}

__device__ __forceinline__ void ldsm_x4(uint32_t* r, uint32_t addr) {
    asm volatile("ldmatrix.sync.aligned.m8n8.x4.shared.b16 {%0,%1,%2,%3}, [%4];"
                 : "=r"(r[0]), "=r"(r[1]), "=r"(r[2]), "=r"(r[3]) : "r"(addr));
}

__device__ __forceinline__ void mma_f16(float* d, const uint32_t* a, const uint32_t* b) {
    asm volatile(
        "mma.sync.aligned.m16n8k16.row.col.f32.f16.f16.f32 "
        "{%0,%1,%2,%3}, {%4,%5,%6,%7}, {%8,%9}, {%0,%1,%2,%3};"
        : "+f"(d[0]), "+f"(d[1]), "+f"(d[2]), "+f"(d[3])
        : "r"(a[0]), "r"(a[1]), "r"(a[2]), "r"(a[3]), "r"(b[0]), "r"(b[1]));
}

// ---------------- CSR build ---------------------------------------------------
// blocks [0,88): zero pad rows of A0/A1; blocks [88,98): zero g_deg
__global__ void zero_init_kernel() {
    if (blockIdx.x < 88) {
        int row = NNODES + blockIdx.x;
        size_t off = (size_t)row * KDUAL + threadIdx.x * 8;
        uint4 z = make_uint4(0, 0, 0, 0);
        *reinterpret_cast<uint4*>(g_A0 + off) = z;
        *reinterpret_cast<uint4*>(g_A1 + off) = z;
    } else {
        int i = (blockIdx.x - 88) * 256 + threadIdx.x;   // 0..2559
        for (int k = i; k < NNODES; k += 2560) g_deg[k] = 0;
    }
}

__global__ void count_deg_kernel(const int* __restrict__ edge_dst) {
    int e = blockIdx.x * blockDim.x + threadIdx.x;
    if (e < NEDGES) atomicAdd(&g_deg[edge_dst[e]], 1);
}

__global__ void build_rowptr_kernel() {
    __shared__ int sums[1024];
    const int tid = threadIdx.x;
    const int CHUNK = 25;
    const int start = tid * CHUNK;
    int s = 0;
    for (int i = 0; i < CHUNK; ++i) {
        int idx = start + i;
        if (idx < NNODES) s += g_deg[idx];
    }
    sums[tid] = s;
    __syncthreads();
    for (int off = 1; off < 1024; off <<= 1) {
        int add = 0;
        if (tid >= off) add = sums[tid - off];
        __syncthreads();
        sums[tid] += add;
        __syncthreads();
    }
    int prefix = (tid > 0) ? sums[tid - 1] : 0;
    for (int i = 0; i < CHUNK; ++i) {
        int idx = start + i;
        if (idx < NNODES) {
            g_rowptr[idx] = prefix;
            int d = g_deg[idx];
            prefix += d;
            g_deginv[idx] = 1.0f / fmaxf((float)d, 1.0f);
            g_fill[idx] = 0;
        }
    }
    if (tid == 1023) g_rowptr[NNODES] = sums[1023];
}

__global__ void fill_csr_kernel(const int* __restrict__ edge_src,
                                const int* __restrict__ edge_dst) {
    int e = blockIdx.x * blockDim.x + threadIdx.x;
    if (e < NEDGES) {
        int dst = edge_dst[e];
        int pos = g_rowptr[dst] + atomicAdd(&g_fill[dst], 1);
        g_col[pos] = edge_src[e];
    }
}

// ---------------- conversions --------------------------------------------------
__global__ __launch_bounds__(256) void convertX_kernel(const float* __restrict__ x) {
    int row = blockIdx.x, t = threadIdx.x;
    float4 v = ((const float4*)(x + (size_t)row * DIM))[t];
    __half2 h0; h0.x = __float2half_rn(v.x); h0.y = __float2half_rn(v.y);
    __half2 h1; h1.x = __float2half_rn(v.z); h1.y = __float2half_rn(v.w);
    size_t off = (size_t)row * KDUAL + t * 4;
    *reinterpret_cast<__half2*>(g_A0 + off)     = h0;
    *reinterpret_cast<__half2*>(g_A0 + off + 2) = h1;
}

// all four W[k][n] fp32 -> B^T[n][koff+k] fp16; z selects (layer, self/neigh)
__global__ void transpose_all_kernel(const float* __restrict__ Ws0,
                                     const float* __restrict__ Wn0,
                                     const float* __restrict__ Ws1,
                                     const float* __restrict__ Wn1) {
    __shared__ float tile[32][33];
    int z = blockIdx.z;
    const float* W = (z == 0) ? Ws0 : (z == 1) ? Wn0 : (z == 2) ? Ws1 : Wn1;
    __half* B = (z < 2) ? g_B0 : g_B1;
    int koff = (z & 1) * DIM;
    int tx = threadIdx.x, ty = threadIdx.y;       // (32, 8)
    int nb = blockIdx.x * 32, kb = blockIdx.y * 32;
    #pragma unroll
    for (int i = 0; i < 32; i += 8)
        tile[ty + i][tx] = W[(size_t)(kb + ty + i) * DIM + nb + tx];
    __syncthreads();
    #pragma unroll
    for (int i = 0; i < 32; i += 8) {
        float v = tile[tx][ty + i];
        B[(size_t)(nb + ty + i) * KDUAL + koff + kb + tx] = __float2half_rn(v);
    }
}

// ---------------- aggregation ---------------------------------------------------
// gather fp16 rows from a[.][0,1024), fp32 accumulate, mean -> fp16 a[.][1024,2048)
__global__ __launch_bounds__(128)
void aggregate_f16_kernel(__half* __restrict__ a) {
    const int node = blockIdx.x;
    const int tid  = threadIdx.x;
    const int beg = g_rowptr[node];
    const int end = g_rowptr[node + 1];
    float acc0[8] = {0.f, 0.f, 0.f, 0.f, 0.f, 0.f, 0.f, 0.f};
    float acc1[8] = {0.f, 0.f, 0.f, 0.f, 0.f, 0.f, 0.f, 0.f};
    int i = beg;
    for (; i + 1 < end; i += 2) {
        int s0 = g_col[i], s1 = g_col[i + 1];
        uint4 r0 = *reinterpret_cast<const uint4*>(a + (size_t)s0 * KDUAL + tid * 8);
        uint4 r1 = *reinterpret_cast<const uint4*>(a + (size_t)s1 * KDUAL + tid * 8);
        const uint32_t* p0 = &r0.x;
        const uint32_t* p1 = &r1.x;
        #pragma unroll
        for (int j = 0; j < 4; ++j) {
            float2 f0 = __half22float2(*reinterpret_cast<const __half2*>(&p0[j]));
            float2 f1 = __half22float2(*reinterpret_cast<const __half2*>(&p1[j]));
            acc0[j * 2]     += f0.x;
            acc0[j * 2 + 1] += f0.y;
            acc1[j * 2]     += f1.x;
            acc1[j * 2 + 1] += f1.y;
        }
    }
    if (i < end) {
        int s0 = g_col[i];
        uint4 r0 = *reinterpret_cast<const uint4*>(a + (size_t)s0 * KDUAL + tid * 8);
        const uint32_t* p0 = &r0.x;
        #pragma unroll
        for (int j = 0; j < 4; ++j) {
            float2 f0 = __half22float2(*reinterpret_cast<const __half2*>(&p0[j]));
            acc0[j * 2]     += f0.x;
            acc0[j * 2 + 1] += f0.y;
        }
    }
    float di = g_deginv[node];
    uint4 outw;
    uint32_t* po = &outw.x;
    #pragma unroll
    for (int j = 0; j < 4; ++j) {
        __half2 h;
        h.x = __float2half_rn((acc0[j * 2]     + acc1[j * 2])     * di);
        h.y = __float2half_rn((acc0[j * 2 + 1] + acc1[j * 2 + 1]) * di);
        po[j] = *reinterpret_cast<uint32_t*>(&h);
    }
    *reinterpret_cast<uint4*>(a + (size_t)node * KDUAL + DIM + tid * 8) = outw;
}

// ---------------- mma.sync fp16 GEMM, K-half --------------------------------------
// phase 0: Cacc[m][n]  = A[:, kbase:kbase+1024) @ B^T slice  (raw fp32 partials)
// phase 1: out = Cacc + A[:, kbase:) @ B^T + bias (relu?) -> C fp32 / OutH fp16
// CTA 128x64, BK=64, 3-stage, 4 warps each 64x32. Grid (16, 196).
__global__ __launch_bounds__(128)
void gemm_f16_kernel(const __half* __restrict__ A,
                     const __half* __restrict__ B,
                     int kbase,
                     const float* __restrict__ bias,
                     float* __restrict__ Cacc,
                     float* __restrict__ C,
                     __half* __restrict__ OutH,
                     int M, int relu, int phase) {
    extern __shared__ __align__(1024) char smem_raw[];
    const uint32_t base = (smem_u32_of(smem_raw) + 1023u) & ~1023u;

    const int t = threadIdx.x;
    const int lane = t & 31;
    const int w = t >> 5;             // 0..3
    const int wm = w >> 1;            // 0..1 -> M offset wm*64
    const int wn = w & 1;             // 0..1 -> N offset wn*32
    const int m0 = blockIdx.y * 128;
    const int n0 = blockIdx.x * 64;

    const char* pA = (const char*)(A + (size_t)m0 * KDUAL + kbase);
    const char* pB = (const char*)(B + (size_t)n0 * KDUAL + kbase);

    float acc[4][4][4];
    #pragma unroll
    for (int i = 0; i < 4; ++i)
        #pragma unroll
        for (int j = 0; j < 4; ++j)
            #pragma unroll
            for (int r = 0; r < 4; ++r) acc[i][j][r] = 0.f;

    const int rowA = lane & 15;
    const int csA  = lane >> 4;
    const int rowB = (lane & 7) | ((lane & 16) >> 1);
    const int csB  = (lane >> 3) & 1;

    auto load_stage = [&](int s) {
        uint32_t sb = base + (s % NBUF) * STAGE_BYTES;
        size_t kb = (size_t)s * 128;          // BK*2 bytes along K
        #pragma unroll
        for (int i = 0; i < 8; ++i) {         // A: 1024 chunks of 16B
            int c = t + i * 128;
            int row = c >> 3, col = (c & 7) * 16;
            cp_async16(sb + sw128((uint32_t)(row * 128 + col)),
                       pA + (size_t)row * 4096 + col + kb);
        }
        #pragma unroll
        for (int i = 0; i < 4; ++i) {         // B: 512 chunks of 16B
            int c = t + i * 128;
            int row = c >> 3, col = (c & 7) * 16;
            cp_async16(sb + 16384 + sw128((uint32_t)(row * 128 + col)),
                       pB + (size_t)row * 4096 + col + kb);
        }
        asm volatile("cp.async.commit_group;" ::: "memory");
    };

    load_stage(0);
    load_stage(1);

    #pragma unroll 1
    for (int s = 0; s < NSTAGE_H; ++s) {
        if (s == NSTAGE_H - 1)
            asm volatile("cp.async.wait_group 0;" ::: "memory");
        else
            asm volatile("cp.async.wait_group 1;" ::: "memory");
        __syncthreads();
        if (s + 2 < NSTAGE_H) load_stage(s + 2);

        uint32_t sb = base + (s % NBUF) * STAGE_BYTES;
        const uint32_t sA = sb, sB = sb + 16384;

        #pragma unroll
        for (int kk = 0; kk < 4; ++kk) {
            uint32_t ah[4][4];
            #pragma unroll
            for (int mf = 0; mf < 4; ++mf) {
                int row = wm * 64 + mf * 16 + rowA;
                ldsm_x4(ah[mf], sA + sw128((uint32_t)(row * 128 + (kk * 2 + csA) * 16)));
            }
            #pragma unroll
            for (int nh = 0; nh < 2; ++nh) {
                int row = wn * 32 + nh * 16 + rowB;
                uint32_t rh[4];
                ldsm_x4(rh, sB + sw128((uint32_t)(row * 128 + (kk * 2 + csB) * 16)));
                #pragma unroll
                for (int mf = 0; mf < 4; ++mf) {
                    mma_f16(acc[mf][nh * 2],     ah[mf], rh);
                    mma_f16(acc[mf][nh * 2 + 1], ah[mf], rh + 2);
                }
            }
        }
        __syncthreads();
    }

    // ---------------- epilogue ----------------
    const int r_in = lane >> 2;
    const int c_in = (lane & 3) * 2;
    #pragma unroll
    for (int mf = 0; mf < 4; ++mf) {
        int mA = m0 + wm * 64 + mf * 16 + r_in;
        int mB = mA + 8;
        #pragma unroll
        for (int nf = 0; nf < 4; ++nf) {
            int n = n0 + wn * 32 + nf * 8 + c_in;
            if (phase == 0) {
                // raw partials (all rows; pad rows harmless)
                *(float2*)(Cacc + (size_t)mA * DIM + n) =
                    make_float2(acc[mf][nf][0], acc[mf][nf][1]);
                *(float2*)(Cacc + (size_t)mB * DIM + n) =
                    make_float2(acc[mf][nf][2], acc[mf][nf][3]);
            } else {
                float2 pA2 = *(const float2*)(Cacc + (size_t)mA * DIM + n);
                float2 pB2 = *(const float2*)(Cacc + (size_t)mB * DIM + n);
                float bx = bias[n], by = bias[n + 1];
                float v0 = acc[mf][nf][0] + pA2.x + bx;
                float v1 = acc[mf][nf][1] + pA2.y + by;
                float v2 = acc[mf][nf][2] + pB2.x + bx;
                float v3 = acc[mf][nf][3] + pB2.y + by;
                if (relu) {
                    v0 = fmaxf(v0, 0.f); v1 = fmaxf(v1, 0.f);
                    v2 = fmaxf(v2, 0.f); v3 = fmaxf(v3, 0.f);
                }
                if (mA < M) {
                    if (C) *(float2*)(C + (size_t)mA * DIM + n) = make_float2(v0, v1);
                    if (OutH) {
                        __half2 h; h.x = __float2half_rn(v0); h.y = __float2half_rn(v1);
                        *reinterpret_cast<__half2*>(OutH + (size_t)mA * KDUAL + n) = h;
                    }
                }
                if (mB < M) {
                    if (C) *(float2*)(C + (size_t)mB * DIM + n) = make_float2(v2, v3);
                    if (OutH) {
                        __half2 h; h.x = __float2half_rn(v2); h.y = __float2half_rn(v3);
                        *reinterpret_cast<__half2*>(OutH + (size_t)mB * KDUAL + n) = h;
                    }
                }
            }
        }
    }
}

// ---------------- launch --------------------------------------------------------
extern "C" void kernel_launch(void* const* d_in, const int* in_sizes, int n_in,
                              void* d_out, int out_size) {
    const float* x    = (const float*)d_in[0];
    const int*   esrc = (const int*)d_in[1];
    const int*   edst = (const int*)d_in[2];
    const float* Ws0  = (const float*)d_in[3];
    const float* Wn0  = (const float*)d_in[4];
    const float* b0   = (const float*)d_in[5];
    const float* Ws1  = (const float*)d_in[6];
    const float* Wn1  = (const float*)d_in[7];
    const float* b1   = (const float*)d_in[8];
    float* out = (float*)d_out;

    __half *a0, *a1, *bw0, *bw1;
    float *cacc;
    cudaGetSymbolAddress((void**)&a0, g_A0);
    cudaGetSymbolAddress((void**)&a1, g_A1);
    cudaGetSymbolAddress((void**)&bw0, g_B0);
    cudaGetSymbolAddress((void**)&bw1, g_B1);
    cudaGetSymbolAddress((void**)&cacc, g_C);

    cudaFuncSetAttribute(gemm_f16_kernel,
                         cudaFuncAttributeMaxDynamicSharedMemorySize, SMEMSZ);

    static cudaStream_t s2 = nullptr;
    static cudaEvent_t ev0 = nullptr, ev_cvt = nullptr,
                       ev_agg0 = nullptr, ev_h = nullptr, ev_agg1 = nullptr;
    if (s2 == nullptr) {
        cudaStreamCreateWithFlags(&s2, cudaStreamNonBlocking);
        cudaEventCreateWithFlags(&ev0,    cudaEventDisableTiming);
        cudaEventCreateWithFlags(&ev_cvt, cudaEventDisableTiming);
        cudaEventCreateWithFlags(&ev_agg0, cudaEventDisableTiming);
        cudaEventCreateWithFlags(&ev_h,   cudaEventDisableTiming);
        cudaEventCreateWithFlags(&ev_agg1, cudaEventDisableTiming);
    }

    dim3 tgrid(32, 32, 4), tblk(32, 8);
    dim3 ggrid(DIM / 64, MPAD / 128);    // (16, 196)

    // main: init + conversions
    zero_init_kernel<<<98, 256>>>();
    cudaEventRecord(ev0, 0);
    convertX_kernel<<<NNODES, 256>>>(x);
    cudaEventRecord(ev_cvt, 0);
    transpose_all_kernel<<<tgrid, tblk>>>(Ws0, Wn0, Ws1, Wn1);

    // s2: CSR chain (needs ev0 for g_deg zeroing), then agg0 (needs convertX)
    cudaStreamWaitEvent(s2, ev0, 0);
    count_deg_kernel<<<(NEDGES + 255) / 256, 256, 0, s2>>>(edst);
    build_rowptr_kernel<<<1, 1024, 0, s2>>>();
    fill_csr_kernel<<<(NEDGES + 255) / 256, 256, 0, s2>>>(esrc, edst);
    cudaStreamWaitEvent(s2, ev_cvt, 0);
    aggregate_f16_kernel<<<NNODES, 128, 0, s2>>>(a0);
    cudaEventRecord(ev_agg0, s2);

    // main: layer-0 GEMM self-half concurrent with agg0
    gemm_f16_kernel<<<ggrid, 128, SMEMSZ>>>(a0, bw0, 0, b0, cacc,
                                            nullptr, nullptr, NNODES, 0, 0);
    cudaStreamWaitEvent(0, ev_agg0, 0);
    gemm_f16_kernel<<<ggrid, 128, SMEMSZ>>>(a0, bw0, DIM, b0, cacc,
                                            nullptr, a1, NNODES, 1, 1);
    cudaEventRecord(ev_h, 0);

    // s2: layer-1 aggregation concurrent with layer-1 self-half GEMM
    cudaStreamWaitEvent(s2, ev_h, 0);
    aggregate_f16_kernel<<<NNODES, 128, 0, s2>>>(a1);
    cudaEventRecord(ev_agg1, s2);

    // main: layer-1 GEMMs
    gemm_f16_kernel<<<ggrid, 128, SMEMSZ>>>(a1, bw1, 0, b1, cacc,
                                            nullptr, nullptr, NNODES, 0, 0);
    cudaStreamWaitEvent(0, ev_agg1, 0);
    gemm_f16_kernel<<<ggrid, 128, SMEMSZ>>>(a1, bw1, DIM, b1, cacc,
                                            out, nullptr, NNODES, 0, 1);
}

// round 16
// speedup vs baseline: 1.0518x; 1.0518x over previous
#include <cuda_runtime.h>
#include <cuda_fp16.h>
#include <cstdint>

#define NNODES 25000
#define NEDGES 400000
#define DIM    1024
#define MPAD   25088          // 196 * 128
#define KDUAL  2048
#define BK     64
#define NSTAGE (KDUAL / BK)   // 32
#define NBUF   3
#define STAGE_BYTES 24576     // A 16K + B 8K
#define SMEMSZ (NBUF * STAGE_BYTES + 1024)

// ---------------- device scratch ---------------------------------------------
__device__ int   g_deg[NNODES];
__device__ float g_deginv[NNODES];
__device__ int   g_rowptr[NNODES + 1];
__device__ int   g_fill[NNODES];
__device__ int   g_col[NEDGES];
__device__ __align__(256) __half g_A0[(size_t)MPAD * KDUAL];   // [x | mean(x)] fp16
__device__ __align__(256) __half g_A1[(size_t)MPAD * KDUAL];   // [h | mean(h)] fp16
__device__ __align__(256) __half g_B0[(size_t)DIM * KDUAL];    // layer-0 [N][K] fp16(W^T)
__device__ __align__(256) __half g_B1[(size_t)DIM * KDUAL];    // layer-1 [N][K] fp16(W^T)

// ---------------- helpers ------------------------------------------------------
__device__ __forceinline__ uint32_t smem_u32_of(const void* p) {
    uint32_t a;
    asm("{ .reg .u64 t; cvta.to.shared.u64 t, %1; cvt.u32.u64 %0, t; }" : "=r"(a) : "l"(p));
    return a;
}

__device__ __forceinline__ uint32_t sw128(uint32_t off) {
    return off ^ ((off >> 3) & 0x70);
}

__device__ __forceinline__ void cp_async16(uint32_t saddr, const void* g) {
    asm volatile("cp.async.cg.shared.global [%0], [%1], 16;" :: "r"(saddr), "l"(g));
}

__device__ __forceinline__ void ldsm_x4(uint32_t* r, uint32_t addr) {
    asm volatile("ldmatrix.sync.aligned.m8n8.x4.shared.b16 {%0,%1,%2,%3}, [%4];"
                 : "=r"(r[0]), "=r"(r[1]), "=r"(r[2]), "=r"(r[3]) : "r"(addr));
}

__device__ __forceinline__ void mma_f16(float* d, const uint32_t* a, const uint32_t* b) {
    asm volatile(
        "mma.sync.aligned.m16n8k16.row.col.f32.f16.f16.f32 "
        "{%0,%1,%2,%3}, {%4,%5,%6,%7}, {%8,%9}, {%0,%1,%2,%3};"
        : "+f"(d[0]), "+f"(d[1]), "+f"(d[2]), "+f"(d[3])
        : "r"(a[0]), "r"(a[1]), "r"(a[2]), "r"(a[3]), "r"(b[0]), "r"(b[1]));
}

// ---------------- convert + init ------------------------------------------------
// blocks [0, NNODES): convert x row -> fp16 A0 cols [0,1024), zero g_deg[row]
// blocks [NNODES, MPAD): zero pad rows of A0/A1
__global__ __launch_bounds__(256) void convert_init_kernel(const float* __restrict__ x) {
    int row = blockIdx.x, t = threadIdx.x;
    if (row < NNODES) {
        float4 v = ((const float4*)(x + (size_t)row * DIM))[t];
        __half2 h0; h0.x = __float2half_rn(v.x); h0.y = __float2half_rn(v.y);
        __half2 h1; h1.x = __float2half_rn(v.z); h1.y = __float2half_rn(v.w);
        size_t off = (size_t)row * KDUAL + t * 4;
        *reinterpret_cast<__half2*>(g_A0 + off)     = h0;
        *reinterpret_cast<__half2*>(g_A0 + off + 2) = h1;
        if (t == 0) g_deg[row] = 0;
    } else {
        size_t off = (size_t)row * KDUAL + t * 8;
        uint4 z = make_uint4(0, 0, 0, 0);
        *reinterpret_cast<uint4*>(g_A0 + off) = z;
        *reinterpret_cast<uint4*>(g_A1 + off) = z;
    }
}

// ---------------- CSR build ---------------------------------------------------
__global__ void count_deg_kernel(const int* __restrict__ edge_dst) {
    int e = blockIdx.x * blockDim.x + threadIdx.x;
    if (e < NEDGES) atomicAdd(&g_deg[edge_dst[e]], 1);
}

__global__ void build_rowptr_kernel() {
    __shared__ int sums[1024];
    const int tid = threadIdx.x;
    const int CHUNK = 25;
    const int start = tid * CHUNK;
    int s = 0;
    for (int i = 0; i < CHUNK; ++i) {
        int idx = start + i;
        if (idx < NNODES) s += g_deg[idx];
    }
    sums[tid] = s;
    __syncthreads();
    for (int off = 1; off < 1024; off <<= 1) {
        int add = 0;
        if (tid >= off) add = sums[tid - off];
        __syncthreads();
        sums[tid] += add;
        __syncthreads();
    }
    int prefix = (tid > 0) ? sums[tid - 1] : 0;
    for (int i = 0; i < CHUNK; ++i) {
        int idx = start + i;
        if (idx < NNODES) {
            g_rowptr[idx] = prefix;
            int d = g_deg[idx];
            prefix += d;
            g_deginv[idx] = 1.0f / fmaxf((float)d, 1.0f);
            g_fill[idx] = 0;
        }
    }
    if (tid == 1023) g_rowptr[NNODES] = sums[1023];
}

__global__ void fill_csr_kernel(const int* __restrict__ edge_src,
                                const int* __restrict__ edge_dst) {
    int e = blockIdx.x * blockDim.x + threadIdx.x;
    if (e < NEDGES) {
        int dst = edge_dst[e];
        int pos = g_rowptr[dst] + atomicAdd(&g_fill[dst], 1);
        g_col[pos] = edge_src[e];
    }
}

// ---------------- weight transposes ---------------------------------------------
// all four W[k][n] fp32 -> B^T[n][koff+k] fp16; z selects (layer, self/neigh)
__global__ void transpose_all_kernel(const float* __restrict__ Ws0,
                                     const float* __restrict__ Wn0,
                                     const float* __restrict__ Ws1,
                                     const float* __restrict__ Wn1) {
    __shared__ float tile[32][33];
    int z = blockIdx.z;
    const float* W = (z == 0) ? Ws0 : (z == 1) ? Wn0 : (z == 2) ? Ws1 : Wn1;
    __half* B = (z < 2) ? g_B0 : g_B1;
    int koff = (z & 1) * DIM;
    int tx = threadIdx.x, ty = threadIdx.y;       // (32, 8)
    int nb = blockIdx.x * 32, kb = blockIdx.y * 32;
    #pragma unroll
    for (int i = 0; i < 32; i += 8)
        tile[ty + i][tx] = W[(size_t)(kb + ty + i) * DIM + nb + tx];
    __syncthreads();
    #pragma unroll
    for (int i = 0; i < 32; i += 8) {
        float v = tile[tx][ty + i];
        B[(size_t)(nb + ty + i) * KDUAL + koff + kb + tx] = __float2half_rn(v);
    }
}

// ---------------- aggregation ---------------------------------------------------
// gather fp16 rows from a[.][0,1024), fp32 accumulate, mean -> fp16 a[.][1024,2048)
__global__ __launch_bounds__(128)
void aggregate_f16_kernel(__half* __restrict__ a) {
    const int node = blockIdx.x;
    const int tid  = threadIdx.x;
    const int beg = g_rowptr[node];
    const int end = g_rowptr[node + 1];
    float acc0[8] = {0.f, 0.f, 0.f, 0.f, 0.f, 0.f, 0.f, 0.f};
    float acc1[8] = {0.f, 0.f, 0.f, 0.f, 0.f, 0.f, 0.f, 0.f};
    int i = beg;
    for (; i + 1 < end; i += 2) {
        int s0 = g_col[i], s1 = g_col[i + 1];
        uint4 r0 = *reinterpret_cast<const uint4*>(a + (size_t)s0 * KDUAL + tid * 8);
        uint4 r1 = *reinterpret_cast<const uint4*>(a + (size_t)s1 * KDUAL + tid * 8);
        const uint32_t* p0 = &r0.x;
        const uint32_t* p1 = &r1.x;
        #pragma unroll
        for (int j = 0; j < 4; ++j) {
            float2 f0 = __half22float2(*reinterpret_cast<const __half2*>(&p0[j]));
            float2 f1 = __half22float2(*reinterpret_cast<const __half2*>(&p1[j]));
            acc0[j * 2]     += f0.x;
            acc0[j * 2 + 1] += f0.y;
            acc1[j * 2]     += f1.x;
            acc1[j * 2 + 1] += f1.y;
        }
    }
    if (i < end) {
        int s0 = g_col[i];
        uint4 r0 = *reinterpret_cast<const uint4*>(a + (size_t)s0 * KDUAL + tid * 8);
        const uint32_t* p0 = &r0.x;
        #pragma unroll
        for (int j = 0; j < 4; ++j) {
            float2 f0 = __half22float2(*reinterpret_cast<const __half2*>(&p0[j]));
            acc0[j * 2]     += f0.x;
            acc0[j * 2 + 1] += f0.y;
        }
    }
    float di = g_deginv[node];
    uint4 outw;
    uint32_t* po = &outw.x;
    #pragma unroll
    for (int j = 0; j < 4; ++j) {
        __half2 h;
        h.x = __float2half_rn((acc0[j * 2]     + acc1[j * 2])     * di);
        h.y = __float2half_rn((acc0[j * 2 + 1] + acc1[j * 2 + 1]) * di);
        po[j] = *reinterpret_cast<uint32_t*>(&h);
    }
    *reinterpret_cast<uint4*>(a + (size_t)node * KDUAL + DIM + tid * 8) = outw;
}

// ---------------- mma.sync fp16 GEMM ---------------------------------------------
// C[M,1024] = A @ B^T + bias; CTA 128x64, BK=64, 3-stage, 4 warps each 64x32.
// Single barrier per stage: buffer s%3 is only overwritten by load_stage(s+3),
// which is issued after iteration s+1's top barrier (all warps done with s).
__global__ __launch_bounds__(128)
void gemm_f16_kernel(const __half* __restrict__ A,
                     const __half* __restrict__ B,
                     const float* __restrict__ bias,
                     float* __restrict__ C,
                     __half* __restrict__ OutH,
                     int M, int relu) {
    extern __shared__ __align__(1024) char smem_raw[];
    const uint32_t base = (smem_u32_of(smem_raw) + 1023u) & ~1023u;

    const int t = threadIdx.x;
    const int lane = t & 31;
    const int w = t >> 5;             // 0..3
    const int wm = w >> 1;            // 0..1 -> M offset wm*64
    const int wn = w & 1;             // 0..1 -> N offset wn*32
    const int m0 = blockIdx.y * 128;
    const int n0 = blockIdx.x * 64;

    const char* pA = (const char*)A + (size_t)m0 * 4096;
    const char* pB = (const char*)B + (size_t)n0 * 4096;

    float acc[4][4][4];
    #pragma unroll
    for (int i = 0; i < 4; ++i)
        #pragma unroll
        for (int j = 0; j < 4; ++j)
            #pragma unroll
            for (int r = 0; r < 4; ++r) acc[i][j][r] = 0.f;

    const int rowA = lane & 15;
    const int csA  = lane >> 4;
    const int rowB = (lane & 7) | ((lane & 16) >> 1);
    const int csB  = (lane >> 3) & 1;

    // stage: A tile 128x64 fp16 (128B rows, SW128) @0, B tile 64x64 @16384
    auto load_stage = [&](int s) {
        uint32_t sb = base + (s % NBUF) * STAGE_BYTES;
        size_t kb = (size_t)s * 128;          // BK*2 bytes along K
        #pragma unroll
        for (int i = 0; i < 8; ++i) {         // A: 1024 chunks of 16B
            int c = t + i * 128;
            int row = c >> 3, col = (c & 7) * 16;
            cp_async16(sb + sw128((uint32_t)(row * 128 + col)),
                       pA + (size_t)row * 4096 + col + kb);
        }
        #pragma unroll
        for (int i = 0; i < 4; ++i) {         // B: 512 chunks of 16B
            int c = t + i * 128;
            int row = c >> 3, col = (c & 7) * 16;
            cp_async16(sb + 16384 + sw128((uint32_t)(row * 128 + col)),
                       pB + (size_t)row * 4096 + col + kb);
        }
        asm volatile("cp.async.commit_group;" ::: "memory");
    };

    load_stage(0);
    load_stage(1);

    #pragma unroll 1
    for (int s = 0; s < NSTAGE; ++s) {
        if (s == NSTAGE - 1)
            asm volatile("cp.async.wait_group 0;" ::: "memory");
        else
            asm volatile("cp.async.wait_group 1;" ::: "memory");
        __syncthreads();                      // all warps done with stage s-1
        if (s + 2 < NSTAGE) load_stage(s + 2);

        uint32_t sb = base + (s % NBUF) * STAGE_BYTES;
        const uint32_t sA = sb, sB = sb + 16384;

        #pragma unroll
        for (int kk = 0; kk < 4; ++kk) {
            uint32_t ah[4][4];
            #pragma unroll
            for (int mf = 0; mf < 4; ++mf) {
                int row = wm * 64 + mf * 16 + rowA;
                ldsm_x4(ah[mf], sA + sw128((uint32_t)(row * 128 + (kk * 2 + csA) * 16)));
            }
            #pragma unroll
            for (int nh = 0; nh < 2; ++nh) {
                int row = wn * 32 + nh * 16 + rowB;
                uint32_t rh[4];
                ldsm_x4(rh, sB + sw128((uint32_t)(row * 128 + (kk * 2 + csB) * 16)));
                #pragma unroll
                for (int mf = 0; mf < 4; ++mf) {
                    mma_f16(acc[mf][nh * 2],     ah[mf], rh);
                    mma_f16(acc[mf][nh * 2 + 1], ah[mf], rh + 2);
                }
            }
        }
    }

    // ---------------- epilogue ----------------
    const int r_in = lane >> 2;
    const int c_in = (lane & 3) * 2;
    #pragma unroll
    for (int mf = 0; mf < 4; ++mf) {
        int mA = m0 + wm * 64 + mf * 16 + r_in;
        int mB = mA + 8;
        #pragma unroll
        for (int nf = 0; nf < 4; ++nf) {
            int n = n0 + wn * 32 + nf * 8 + c_in;
            float bx = bias[n], by = bias[n + 1];
            float v0 = acc[mf][nf][0] + bx, v1 = acc[mf][nf][1] + by;
            float v2 = acc[mf][nf][2] + bx, v3 = acc[mf][nf][3] + by;
            if (relu) {
                v0 = fmaxf(v0, 0.f); v1 = fmaxf(v1, 0.f);
                v2 = fmaxf(v2, 0.f); v3 = fmaxf(v3, 0.f);
            }
            if (mA < M) {
                if (C) *(float2*)(C + (size_t)mA * DIM + n) = make_float2(v0, v1);
                if (OutH) {
                    __half2 h; h.x = __float2half_rn(v0); h.y = __float2half_rn(v1);
                    *reinterpret_cast<__half2*>(OutH + (size_t)mA * KDUAL + n) = h;
                }
            }
            if (mB < M) {
                if (C) *(float2*)(C + (size_t)mB * DIM + n) = make_float2(v2, v3);
                if (OutH) {
                    __half2 h; h.x = __float2half_rn(v2); h.y = __float2half_rn(v3);
                    *reinterpret_cast<__half2*>(OutH + (size_t)mB * KDUAL + n) = h;
                }
            }
        }
    }
}

// ---------------- launch --------------------------------------------------------
extern "C" void kernel_launch(void* const* d_in, const int* in_sizes, int n_in,
                              void* d_out, int out_size) {
    const float* x    = (const float*)d_in[0];
    const int*   esrc = (const int*)d_in[1];
    const int*   edst = (const int*)d_in[2];
    const float* Ws0  = (const float*)d_in[3];
    const float* Wn0  = (const float*)d_in[4];
    const float* b0   = (const float*)d_in[5];
    const float* Ws1  = (const float*)d_in[6];
    const float* Wn1  = (const float*)d_in[7];
    const float* b1   = (const float*)d_in[8];
    float* out = (float*)d_out;

    __half *a0, *a1, *bw0, *bw1;
    cudaGetSymbolAddress((void**)&a0, g_A0);
    cudaGetSymbolAddress((void**)&a1, g_A1);
    cudaGetSymbolAddress((void**)&bw0, g_B0);
    cudaGetSymbolAddress((void**)&bw1, g_B1);

    cudaFuncSetAttribute(gemm_f16_kernel,
                         cudaFuncAttributeMaxDynamicSharedMemorySize, SMEMSZ);

    // convert x -> fp16 (+ zero deg, zero pads), then CSR chain
    convert_init_kernel<<<MPAD, 256>>>(x);
    count_deg_kernel<<<(NEDGES + 255) / 256, 256>>>(edst);
    build_rowptr_kernel<<<1, 1024>>>();
    fill_csr_kernel<<<(NEDGES + 255) / 256, 256>>>(esrc, edst);

    // layer 0 aggregation, then weight transposes right before GEMM
    aggregate_f16_kernel<<<NNODES, 128>>>(a0);
    dim3 tgrid(32, 32, 4), tblk(32, 8);
    transpose_all_kernel<<<tgrid, tblk>>>(Ws0, Wn0, Ws1, Wn1);

    dim3 ggrid(DIM / 64, MPAD / 128);    // (16, 196)

    // layer 0: h (fp16) -> A1 cols [0,1024)
    gemm_f16_kernel<<<ggrid, 128, SMEMSZ>>>(a0, bw0, b0, nullptr, a1, NNODES, 1);

    // layer 1
    aggregate_f16_kernel<<<NNODES, 128>>>(a1);
    gemm_f16_kernel<<<ggrid, 128, SMEMSZ>>>(a1, bw1, b1, out, nullptr, NNODES, 0);
}